// round 1
// baseline (speedup 1.0000x reference)
#include <cuda_runtime.h>
#include <math.h>

#define B_ 4
#define S_ 2048
#define D_ 512
#define H_ 8
#define E_ 64

// Scratch (static device memory — allocation-free per harness rules)
__device__ float g_q[B_*H_*S_*E_];
__device__ float g_k[B_*H_*S_*E_];
__device__ float g_v[B_*H_*S_*E_];
__device__ float g_att[B_*S_*D_];

// ---------------------------------------------------------------------------
// Kernel 1: fused QKV projection.
// grid = (S/64, H, B), 256 threads. Each block: 64 rows x 64 cols (E) for one
// head, for q, k and v simultaneously (x tile loaded once, 3 weight tiles).
// ---------------------------------------------------------------------------
__global__ __launch_bounds__(256) void qkv_kernel(
    const float* __restrict__ x,
    const float* __restrict__ Wq, const float* __restrict__ bq,
    const float* __restrict__ Wk, const float* __restrict__ bk,
    const float* __restrict__ Wv, const float* __restrict__ bv)
{
    __shared__ float xs[64][36];   // padded rows, [r][k]
    __shared__ float wqs[32][64];  // [k][e]
    __shared__ float wks[32][64];
    __shared__ float wvs[32][64];

    const int sb = blockIdx.x, h = blockIdx.y, b = blockIdx.z;
    const int tid = threadIdx.x;
    const int tx = tid & 15, ty = tid >> 4;

    float aq[4][4] = {}, ak[4][4] = {}, av[4][4] = {};

    const float* xb  = x  + ((size_t)(b*S_) + (size_t)sb*64) * D_;
    const float* wqb = Wq + (size_t)h * D_ * E_;
    const float* wkb = Wk + (size_t)h * D_ * E_;
    const float* wvb = Wv + (size_t)h * D_ * E_;

    for (int kc = 0; kc < D_; kc += 32) {
        __syncthreads();
        #pragma unroll
        for (int it = 0; it < 2; it++) {
            int idx = tid + it*256;
            int r = idx >> 3, q = idx & 7;
            *(float4*)&xs[r][q*4] = *(const float4*)(xb + (size_t)r*D_ + kc + q*4);
            int k = idx >> 4, f = idx & 15;
            *(float4*)&wqs[k][f*4] = *(const float4*)(wqb + (size_t)(kc+k)*E_ + f*4);
            *(float4*)&wks[k][f*4] = *(const float4*)(wkb + (size_t)(kc+k)*E_ + f*4);
            *(float4*)&wvs[k][f*4] = *(const float4*)(wvb + (size_t)(kc+k)*E_ + f*4);
        }
        __syncthreads();
        #pragma unroll
        for (int k = 0; k < 32; k++) {
            float aa[4];
            #pragma unroll
            for (int i = 0; i < 4; i++) aa[i] = xs[ty*4+i][k];
            float4 q4 = *(const float4*)&wqs[k][tx*4];
            float4 k4 = *(const float4*)&wks[k][tx*4];
            float4 v4 = *(const float4*)&wvs[k][tx*4];
            float qv[4] = {q4.x,q4.y,q4.z,q4.w};
            float kv[4] = {k4.x,k4.y,k4.z,k4.w};
            float vv[4] = {v4.x,v4.y,v4.z,v4.w};
            #pragma unroll
            for (int i = 0; i < 4; i++) {
                #pragma unroll
                for (int j = 0; j < 4; j++) {
                    aq[i][j] += aa[i]*qv[j];
                    ak[i][j] += aa[i]*kv[j];
                    av[i][j] += aa[i]*vv[j];
                }
            }
        }
    }

    float4 bq4 = *(const float4*)(bq + h*E_ + tx*4);
    float4 bk4 = *(const float4*)(bk + h*E_ + tx*4);
    float4 bv4 = *(const float4*)(bv + h*E_ + tx*4);
    size_t base = ((size_t)(b*H_ + h)*S_ + (size_t)sb*64);
    #pragma unroll
    for (int i = 0; i < 4; i++) {
        size_t row = base + ty*4 + i;
        *(float4*)&g_q[row*E_ + tx*4] =
            make_float4(aq[i][0]+bq4.x, aq[i][1]+bq4.y, aq[i][2]+bq4.z, aq[i][3]+bq4.w);
        *(float4*)&g_k[row*E_ + tx*4] =
            make_float4(ak[i][0]+bk4.x, ak[i][1]+bk4.y, ak[i][2]+bk4.z, ak[i][3]+bk4.w);
        *(float4*)&g_v[row*E_ + tx*4] =
            make_float4(av[i][0]+bv4.x, av[i][1]+bv4.y, av[i][2]+bv4.z, av[i][3]+bv4.w);
    }
}

// ---------------------------------------------------------------------------
// Kernel 2: causal flash attention, one (b, h, 64-query block) per CTA.
// Online softmax; only tiles t <= qb processed (causal skip). 256 threads,
// each owns a 4x4 of the 64x64 score tile and a 4x4 of the 64x64 output tile.
// ---------------------------------------------------------------------------
#define SMEM_FLOATS (3*64*68 + 64*64)

__global__ __launch_bounds__(256) void attn_kernel()
{
    extern __shared__ float smf[];
    float* Qs = smf;               // [64][68]  (row r, dim e), pre-scaled
    float* Ks = smf + 64*68;       // [64][68]  (row c, dim e)
    float* Vs = smf + 2*64*68;     // [64][68]  (row c, dim e)
    float* Ps = smf + 3*64*68;     // [64][64]  (row r, col c)

    const int qb = blockIdx.x, h = blockIdx.y, b = blockIdx.z;
    const int tid = threadIdx.x;
    const int tx = tid & 15, ty = tid >> 4;
    const float scale = rsqrtf((float)D_);

    const size_t bh = (size_t)(b*H_ + h) * S_;

    #pragma unroll
    for (int it = 0; it < 4; it++) {
        int idx = tid + it*256;
        int r = idx >> 4, f = idx & 15;
        float4 v4 = *(const float4*)&g_q[(bh + (size_t)qb*64 + r)*E_ + f*4];
        v4.x *= scale; v4.y *= scale; v4.z *= scale; v4.w *= scale;
        *(float4*)&Qs[r*68 + f*4] = v4;
    }

    float m[4], l[4], o[4][4];
    #pragma unroll
    for (int i = 0; i < 4; i++) {
        m[i] = -1e30f; l[i] = 0.f;
        #pragma unroll
        for (int j = 0; j < 4; j++) o[i][j] = 0.f;
    }

    for (int t = 0; t <= qb; t++) {
        __syncthreads();  // also orders Q-tile stores before first use
        #pragma unroll
        for (int it = 0; it < 4; it++) {
            int idx = tid + it*256;
            int r = idx >> 4, f = idx & 15;
            *(float4*)&Ks[r*68 + f*4] = *(const float4*)&g_k[(bh + (size_t)t*64 + r)*E_ + f*4];
            *(float4*)&Vs[r*68 + f*4] = *(const float4*)&g_v[(bh + (size_t)t*64 + r)*E_ + f*4];
        }
        __syncthreads();

        // Scores: s = (Q*scale) @ K^T  (64x64x64)
        float s[4][4] = {};
        #pragma unroll
        for (int e4 = 0; e4 < 16; e4++) {
            float4 a[4], bb[4];
            #pragma unroll
            for (int i = 0; i < 4; i++) a[i]  = *(const float4*)&Qs[(ty*4+i)*68 + e4*4];
            #pragma unroll
            for (int j = 0; j < 4; j++) bb[j] = *(const float4*)&Ks[(tx*4+j)*68 + e4*4];
            #pragma unroll
            for (int i = 0; i < 4; i++) {
                #pragma unroll
                for (int j = 0; j < 4; j++) {
                    s[i][j] += a[i].x*bb[j].x + a[i].y*bb[j].y
                             + a[i].z*bb[j].z + a[i].w*bb[j].w;
                }
            }
        }

        if (t == qb) {  // causal mask only on the diagonal tile
            #pragma unroll
            for (int i = 0; i < 4; i++)
                #pragma unroll
                for (int j = 0; j < 4; j++)
                    if (tx*4+j > ty*4+i) s[i][j] = -1e30f;
        }

        // Online softmax per row (16-lane shuffle reduction across tx)
        #pragma unroll
        for (int i = 0; i < 4; i++) {
            float tm = fmaxf(fmaxf(s[i][0], s[i][1]), fmaxf(s[i][2], s[i][3]));
            #pragma unroll
            for (int off = 8; off > 0; off >>= 1)
                tm = fmaxf(tm, __shfl_xor_sync(0xffffffffu, tm, off));
            float mn = fmaxf(m[i], tm);
            float fc = __expf(m[i] - mn);
            float p0 = __expf(s[i][0] - mn);
            float p1 = __expf(s[i][1] - mn);
            float p2 = __expf(s[i][2] - mn);
            float p3 = __expf(s[i][3] - mn);
            float ts = (p0 + p1) + (p2 + p3);
            #pragma unroll
            for (int off = 8; off > 0; off >>= 1)
                ts += __shfl_xor_sync(0xffffffffu, ts, off);
            l[i] = l[i]*fc + ts;
            m[i] = mn;
            o[i][0] *= fc; o[i][1] *= fc; o[i][2] *= fc; o[i][3] *= fc;
            *(float4*)&Ps[(ty*4+i)*64 + tx*4] = make_float4(p0, p1, p2, p3);
        }
        __syncthreads();

        // O += P @ V (64x64x64)
        #pragma unroll 4
        for (int c = 0; c < 64; c++) {
            float4 vv = *(const float4*)&Vs[c*68 + tx*4];
            float a0 = Ps[(ty*4+0)*64 + c];
            float a1 = Ps[(ty*4+1)*64 + c];
            float a2 = Ps[(ty*4+2)*64 + c];
            float a3 = Ps[(ty*4+3)*64 + c];
            o[0][0] += a0*vv.x; o[0][1] += a0*vv.y; o[0][2] += a0*vv.z; o[0][3] += a0*vv.w;
            o[1][0] += a1*vv.x; o[1][1] += a1*vv.y; o[1][2] += a1*vv.z; o[1][3] += a1*vv.w;
            o[2][0] += a2*vv.x; o[2][1] += a2*vv.y; o[2][2] += a2*vv.z; o[2][3] += a2*vv.w;
            o[3][0] += a3*vv.x; o[3][1] += a3*vv.y; o[3][2] += a3*vv.z; o[3][3] += a3*vv.w;
        }
    }

    // Normalize and write concat-layout [B, S, D] with head-major columns
    #pragma unroll
    for (int i = 0; i < 4; i++) {
        float inv = 1.f / l[i];
        size_t row = (size_t)b*S_ + (size_t)qb*64 + ty*4 + i;
        *(float4*)&g_att[row*D_ + h*E_ + tx*4] =
            make_float4(o[i][0]*inv, o[i][1]*inv, o[i][2]*inv, o[i][3]*inv);
    }
}

// ---------------------------------------------------------------------------
// Kernel 3: output projection  out = g_att @ Wo + bo   (8192 x 512 x 512)
// grid = (N/64, M/64), 256 threads, 4x4 per thread.
// ---------------------------------------------------------------------------
__global__ __launch_bounds__(256) void proj_kernel(
    const float* __restrict__ Wo, const float* __restrict__ bo,
    float* __restrict__ out)
{
    __shared__ float As[64][36];
    __shared__ float Bs[32][64];

    const int nb = blockIdx.x, mb = blockIdx.y;
    const int tid = threadIdx.x;
    const int tx = tid & 15, ty = tid >> 4;

    float acc[4][4] = {};
    const float* ab = g_att + (size_t)mb*64 * D_;

    for (int kc = 0; kc < D_; kc += 32) {
        __syncthreads();
        #pragma unroll
        for (int it = 0; it < 2; it++) {
            int idx = tid + it*256;
            int r = idx >> 3, q = idx & 7;
            *(float4*)&As[r][q*4] = *(const float4*)(ab + (size_t)r*D_ + kc + q*4);
            int k = idx >> 4, f = idx & 15;
            *(float4*)&Bs[k][f*4] = *(const float4*)(Wo + (size_t)(kc+k)*D_ + nb*64 + f*4);
        }
        __syncthreads();
        #pragma unroll
        for (int k = 0; k < 32; k++) {
            float a0 = As[ty*4+0][k], a1 = As[ty*4+1][k];
            float a2 = As[ty*4+2][k], a3 = As[ty*4+3][k];
            float4 b4 = *(const float4*)&Bs[k][tx*4];
            acc[0][0] += a0*b4.x; acc[0][1] += a0*b4.y; acc[0][2] += a0*b4.z; acc[0][3] += a0*b4.w;
            acc[1][0] += a1*b4.x; acc[1][1] += a1*b4.y; acc[1][2] += a1*b4.z; acc[1][3] += a1*b4.w;
            acc[2][0] += a2*b4.x; acc[2][1] += a2*b4.y; acc[2][2] += a2*b4.z; acc[2][3] += a2*b4.w;
            acc[3][0] += a3*b4.x; acc[3][1] += a3*b4.y; acc[3][2] += a3*b4.z; acc[3][3] += a3*b4.w;
        }
    }

    float4 bo4 = *(const float4*)(bo + nb*64 + tx*4);
    #pragma unroll
    for (int i = 0; i < 4; i++) {
        size_t row = (size_t)mb*64 + ty*4 + i;
        *(float4*)&out[row*D_ + nb*64 + tx*4] =
            make_float4(acc[i][0]+bo4.x, acc[i][1]+bo4.y, acc[i][2]+bo4.z, acc[i][3]+bo4.w);
    }
}

// ---------------------------------------------------------------------------
extern "C" void kernel_launch(void* const* d_in, const int* in_sizes, int n_in,
                              void* d_out, int out_size)
{
    const float* x  = (const float*)d_in[0];
    const float* Wq = (const float*)d_in[1];
    const float* bq = (const float*)d_in[2];
    const float* Wk = (const float*)d_in[3];
    const float* bk = (const float*)d_in[4];
    const float* Wv = (const float*)d_in[5];
    const float* bv = (const float*)d_in[6];
    const float* Wo = (const float*)d_in[7];
    const float* bo = (const float*)d_in[8];
    float* out = (float*)d_out;

    (void)in_sizes; (void)n_in; (void)out_size;

    cudaFuncSetAttribute(attn_kernel,
                         cudaFuncAttributeMaxDynamicSharedMemorySize,
                         SMEM_FLOATS * (int)sizeof(float));

    dim3 g1(S_/64, H_, B_);
    qkv_kernel<<<g1, 256>>>(x, Wq, bq, Wk, bk, Wv, bv);

    attn_kernel<<<g1, 256, SMEM_FLOATS * sizeof(float)>>>();

    dim3 g3(D_/64, (B_*S_)/64);
    proj_kernel<<<g3, 256>>>(Wo, bo, out);
}

// round 2
// speedup vs baseline: 1.9773x; 1.9773x over previous
#include <cuda_runtime.h>
#include <math.h>
#include <stdint.h>

#define B_ 4
#define S_ 2048
#define D_ 512
#define H_ 8
#define E_ 64

// Scratch (static device memory — allocation-free per harness rules)
__device__ float g_q[B_*H_*S_*E_];
__device__ float g_k[B_*H_*S_*E_];
__device__ float g_v[B_*H_*S_*E_];
__device__ float g_att[B_*S_*D_];

// ---------------------------------------------------------------------------
// Helpers: tf32 convert + warp mma m16n8k8 (tf32 in, f32 accum)
// ---------------------------------------------------------------------------
__device__ __forceinline__ uint32_t f2tf32(float f) {
    uint32_t u;
    asm("cvt.rna.tf32.f32 %0, %1;" : "=r"(u) : "f"(f));
    return u;
}

__device__ __forceinline__ void mma_tf32(float c[4],
                                         uint32_t a0, uint32_t a1,
                                         uint32_t a2, uint32_t a3,
                                         uint32_t b0, uint32_t b1) {
    asm volatile(
        "mma.sync.aligned.m16n8k8.row.col.f32.tf32.tf32.f32 "
        "{%0,%1,%2,%3}, {%4,%5,%6,%7}, {%8,%9}, {%0,%1,%2,%3};"
        : "+f"(c[0]), "+f"(c[1]), "+f"(c[2]), "+f"(c[3])
        : "r"(a0), "r"(a1), "r"(a2), "r"(a3), "r"(b0), "r"(b1));
}

// ---------------------------------------------------------------------------
// Kernel 1: fused QKV projection (unchanged from R1 — 280us, fma 57%)
// ---------------------------------------------------------------------------
__global__ __launch_bounds__(256) void qkv_kernel(
    const float* __restrict__ x,
    const float* __restrict__ Wq, const float* __restrict__ bq,
    const float* __restrict__ Wk, const float* __restrict__ bk,
    const float* __restrict__ Wv, const float* __restrict__ bv)
{
    __shared__ float xs[64][36];
    __shared__ float wqs[32][64];
    __shared__ float wks[32][64];
    __shared__ float wvs[32][64];

    const int sb = blockIdx.x, h = blockIdx.y, b = blockIdx.z;
    const int tid = threadIdx.x;
    const int tx = tid & 15, ty = tid >> 4;

    float aq[4][4] = {}, ak[4][4] = {}, av[4][4] = {};

    const float* xb  = x  + ((size_t)(b*S_) + (size_t)sb*64) * D_;
    const float* wqb = Wq + (size_t)h * D_ * E_;
    const float* wkb = Wk + (size_t)h * D_ * E_;
    const float* wvb = Wv + (size_t)h * D_ * E_;

    for (int kc = 0; kc < D_; kc += 32) {
        __syncthreads();
        #pragma unroll
        for (int it = 0; it < 2; it++) {
            int idx = tid + it*256;
            int r = idx >> 3, q = idx & 7;
            *(float4*)&xs[r][q*4] = *(const float4*)(xb + (size_t)r*D_ + kc + q*4);
            int k = idx >> 4, f = idx & 15;
            *(float4*)&wqs[k][f*4] = *(const float4*)(wqb + (size_t)(kc+k)*E_ + f*4);
            *(float4*)&wks[k][f*4] = *(const float4*)(wkb + (size_t)(kc+k)*E_ + f*4);
            *(float4*)&wvs[k][f*4] = *(const float4*)(wvb + (size_t)(kc+k)*E_ + f*4);
        }
        __syncthreads();
        #pragma unroll
        for (int k = 0; k < 32; k++) {
            float aa[4];
            #pragma unroll
            for (int i = 0; i < 4; i++) aa[i] = xs[ty*4+i][k];
            float4 q4 = *(const float4*)&wqs[k][tx*4];
            float4 k4 = *(const float4*)&wks[k][tx*4];
            float4 v4 = *(const float4*)&wvs[k][tx*4];
            float qv[4] = {q4.x,q4.y,q4.z,q4.w};
            float kv[4] = {k4.x,k4.y,k4.z,k4.w};
            float vv[4] = {v4.x,v4.y,v4.z,v4.w};
            #pragma unroll
            for (int i = 0; i < 4; i++) {
                #pragma unroll
                for (int j = 0; j < 4; j++) {
                    aq[i][j] += aa[i]*qv[j];
                    ak[i][j] += aa[i]*kv[j];
                    av[i][j] += aa[i]*vv[j];
                }
            }
        }
    }

    float4 bq4 = *(const float4*)(bq + h*E_ + tx*4);
    float4 bk4 = *(const float4*)(bk + h*E_ + tx*4);
    float4 bv4 = *(const float4*)(bv + h*E_ + tx*4);
    size_t base = ((size_t)(b*H_ + h)*S_ + (size_t)sb*64);
    #pragma unroll
    for (int i = 0; i < 4; i++) {
        size_t row = base + ty*4 + i;
        *(float4*)&g_q[row*E_ + tx*4] =
            make_float4(aq[i][0]+bq4.x, aq[i][1]+bq4.y, aq[i][2]+bq4.z, aq[i][3]+bq4.w);
        *(float4*)&g_k[row*E_ + tx*4] =
            make_float4(ak[i][0]+bk4.x, ak[i][1]+bk4.y, ak[i][2]+bk4.z, ak[i][3]+bk4.w);
        *(float4*)&g_v[row*E_ + tx*4] =
            make_float4(av[i][0]+bv4.x, av[i][1]+bv4.y, av[i][2]+bv4.z, av[i][3]+bv4.w);
    }
}

// ---------------------------------------------------------------------------
// Kernel 2: causal flash attention with tf32 warp MMA.
// CTA = 128 queries x one (b,h). 8 warps; warp w owns rows [w*16, w*16+16).
// Each warp computes its 16 rows against ALL 64 keys of the current tile, so
// softmax is entirely warp-local. K/V tiles stored in smem in B-fragment
// order (conflict-free LDS.64 at mma time). P is permuted C->A layout with
// register shuffles (no smem round trip).
// ---------------------------------------------------------------------------
__global__ __launch_bounds__(256) void attn_kernel()
{
    __shared__ uint32_t Kf[4096];   // 64x64 tf32, fragment-ordered
    __shared__ uint32_t Vf[4096];

    const int qb = (S_/128 - 1) - blockIdx.x;   // big blocks first (causal balance)
    const int h = blockIdx.y, b = blockIdx.z;
    const int tid = threadIdx.x;
    const int warp = tid >> 5, lane = tid & 31;
    const int g = lane >> 2, tg = lane & 3;
    const float scale = rsqrtf((float)D_);
    const size_t bh = (size_t)(b*H_ + h) * S_;

    const int qrow0 = qb*128 + warp*16 + g;     // global query row (reg 0/.. half)
    // second row half = qrow0 + 8

    // --- Q fragments (pre-scaled, tf32), loaded once ---
    uint32_t aq[8][4];
    {
        const float* q0 = &g_q[(bh + qrow0) * E_];
        const float* q1 = q0 + 8 * E_;
        #pragma unroll
        for (int ks = 0; ks < 8; ks++) {
            aq[ks][0] = f2tf32(q0[ks*8 + tg]     * scale);
            aq[ks][1] = f2tf32(q1[ks*8 + tg]     * scale);
            aq[ks][2] = f2tf32(q0[ks*8 + tg + 4] * scale);
            aq[ks][3] = f2tf32(q1[ks*8 + tg + 4] * scale);
        }
    }

    float o[8][4];
    #pragma unroll
    for (int nt = 0; nt < 8; nt++) { o[nt][0]=o[nt][1]=o[nt][2]=o[nt][3]=0.f; }
    float m0 = -1e30f, m1 = -1e30f, l0 = 0.f, l1 = 0.f;

    const int nk = 2*qb + 2;   // 64-key tiles covering keys [0, qb*128+128)

    for (int t = 0; t < nk; t++) {
        __syncthreads();
        // --- load K/V tile into fragment-ordered smem ---
        #pragma unroll
        for (int it = 0; it < 4; it++) {
            int idx4 = it*256 + tid;
            int tt = idx4 >> 4;          // key row within tile, 0..63
            int e4 = idx4 & 15;
            size_t gidx = (bh + (size_t)t*64 + tt) * E_ + e4*4;
            float4 k4 = *(const float4*)&g_k[gidx];
            float4 v4 = *(const float4*)&g_v[gidx];
            const float* kp = (const float*)&k4;
            const float* vp = (const float*)&v4;
            #pragma unroll
            for (int j = 0; j < 4; j++) {
                int e = e4*4 + j;
                // K as B of QK^T: B[k=e][n=t]
                int nt  = tt >> 3, gg  = tt & 7;
                int ks  = e  >> 3, el  = e  & 7;
                int tgg = el & 3,  r   = el >> 2;
                Kf[(nt*8 + ks)*64 + (gg*4 + tgg)*2 + r] = f2tf32(kp[j]);
                // V as B of PV: B[k=t][n=e]
                int ks2 = tt >> 3, tl = tt & 7;
                int tg2 = tl & 3,  r2 = tl >> 2;
                int nt2 = e  >> 3, g2 = e  & 7;
                Vf[(nt2*8 + ks2)*64 + (g2*4 + tg2)*2 + r2] = f2tf32(vp[j]);
            }
        }
        __syncthreads();

        // --- S = Q @ K^T  (16 x 64 per warp) ---
        float s[8][4];
        #pragma unroll
        for (int nt = 0; nt < 8; nt++) { s[nt][0]=s[nt][1]=s[nt][2]=s[nt][3]=0.f; }
        #pragma unroll
        for (int ks = 0; ks < 8; ks++) {
            #pragma unroll
            for (int nt = 0; nt < 8; nt++) {
                uint2 bb = *(const uint2*)&Kf[(nt*8 + ks)*64 + lane*2];
                mma_tf32(s[nt], aq[ks][0], aq[ks][1], aq[ks][2], aq[ks][3],
                         bb.x, bb.y);
            }
        }

        // --- causal mask (only tiles that can cross the diagonal) ---
        if (t >= 2*qb) {
            #pragma unroll
            for (int nt = 0; nt < 8; nt++) {
                int c = t*64 + nt*8 + 2*tg;
                if (c     > qrow0)     s[nt][0] = -1e30f;
                if (c + 1 > qrow0)     s[nt][1] = -1e30f;
                if (c     > qrow0 + 8) s[nt][2] = -1e30f;
                if (c + 1 > qrow0 + 8) s[nt][3] = -1e30f;
            }
        }

        // --- online softmax (warp-local; rows g and g+8) ---
        float tm0 = -1e30f, tm1 = -1e30f;
        #pragma unroll
        for (int nt = 0; nt < 8; nt++) {
            tm0 = fmaxf(tm0, fmaxf(s[nt][0], s[nt][1]));
            tm1 = fmaxf(tm1, fmaxf(s[nt][2], s[nt][3]));
        }
        tm0 = fmaxf(tm0, __shfl_xor_sync(0xffffffffu, tm0, 1));
        tm0 = fmaxf(tm0, __shfl_xor_sync(0xffffffffu, tm0, 2));
        tm1 = fmaxf(tm1, __shfl_xor_sync(0xffffffffu, tm1, 1));
        tm1 = fmaxf(tm1, __shfl_xor_sync(0xffffffffu, tm1, 2));

        float mn0 = fmaxf(m0, tm0), mn1 = fmaxf(m1, tm1);
        float fc0 = __expf(m0 - mn0), fc1 = __expf(m1 - mn1);
        m0 = mn0; m1 = mn1;

        float rs0 = 0.f, rs1 = 0.f;
        #pragma unroll
        for (int nt = 0; nt < 8; nt++) {
            float p0 = __expf(s[nt][0] - mn0);
            float p1 = __expf(s[nt][1] - mn0);
            float p2 = __expf(s[nt][2] - mn1);
            float p3 = __expf(s[nt][3] - mn1);
            s[nt][0] = p0; s[nt][1] = p1; s[nt][2] = p2; s[nt][3] = p3;
            rs0 += p0 + p1; rs1 += p2 + p3;
        }
        rs0 += __shfl_xor_sync(0xffffffffu, rs0, 1);
        rs0 += __shfl_xor_sync(0xffffffffu, rs0, 2);
        rs1 += __shfl_xor_sync(0xffffffffu, rs1, 1);
        rs1 += __shfl_xor_sync(0xffffffffu, rs1, 2);
        l0 = l0*fc0 + rs0;
        l1 = l1*fc1 + rs1;
        #pragma unroll
        for (int nt = 0; nt < 8; nt++) {
            o[nt][0] *= fc0; o[nt][1] *= fc0;
            o[nt][2] *= fc1; o[nt][3] *= fc1;
        }

        // --- O += P @ V: permute P (C-layout) -> A-layout via shuffles ---
        const int srcA = (lane & ~3) | (tg >> 1);
        const int srcB = srcA + 2;
        const bool hi = (tg & 1);
        #pragma unroll
        for (int ks = 0; ks < 8; ks++) {
            float x0 = __shfl_sync(0xffffffffu, s[ks][0], srcA);
            float x1 = __shfl_sync(0xffffffffu, s[ks][1], srcA);
            float z0 = __shfl_sync(0xffffffffu, s[ks][2], srcA);
            float z1 = __shfl_sync(0xffffffffu, s[ks][3], srcA);
            float y0 = __shfl_sync(0xffffffffu, s[ks][0], srcB);
            float y1 = __shfl_sync(0xffffffffu, s[ks][1], srcB);
            float w0 = __shfl_sync(0xffffffffu, s[ks][2], srcB);
            float w1 = __shfl_sync(0xffffffffu, s[ks][3], srcB);
            uint32_t pa0 = f2tf32(hi ? x1 : x0);   // P[g   ][8ks+tg]
            uint32_t pa1 = f2tf32(hi ? z1 : z0);   // P[g+8 ][8ks+tg]
            uint32_t pa2 = f2tf32(hi ? y1 : y0);   // P[g   ][8ks+tg+4]
            uint32_t pa3 = f2tf32(hi ? w1 : w0);   // P[g+8 ][8ks+tg+4]
            #pragma unroll
            for (int nt = 0; nt < 8; nt++) {
                uint2 bb = *(const uint2*)&Vf[(nt*8 + ks)*64 + lane*2];
                mma_tf32(o[nt], pa0, pa1, pa2, pa3, bb.x, bb.y);
            }
        }
    }

    // --- normalize + write concat layout [B,S,D], head-major columns ---
    const float inv0 = 1.f / l0, inv1 = 1.f / l1;
    const size_t row0 = (size_t)b*S_ + (size_t)qb*128 + warp*16 + g;
    const size_t row1 = row0 + 8;
    #pragma unroll
    for (int nt = 0; nt < 8; nt++) {
        int col = h*E_ + nt*8 + 2*tg;
        *(float2*)&g_att[row0*D_ + col] = make_float2(o[nt][0]*inv0, o[nt][1]*inv0);
        *(float2*)&g_att[row1*D_ + col] = make_float2(o[nt][2]*inv1, o[nt][3]*inv1);
    }
}

// ---------------------------------------------------------------------------
// Kernel 3: output projection (unchanged from R1)
// ---------------------------------------------------------------------------
__global__ __launch_bounds__(256) void proj_kernel(
    const float* __restrict__ Wo, const float* __restrict__ bo,
    float* __restrict__ out)
{
    __shared__ float As[64][36];
    __shared__ float Bs[32][64];

    const int nb = blockIdx.x, mb = blockIdx.y;
    const int tid = threadIdx.x;
    const int tx = tid & 15, ty = tid >> 4;

    float acc[4][4] = {};
    const float* ab = g_att + (size_t)mb*64 * D_;

    for (int kc = 0; kc < D_; kc += 32) {
        __syncthreads();
        #pragma unroll
        for (int it = 0; it < 2; it++) {
            int idx = tid + it*256;
            int r = idx >> 3, q = idx & 7;
            *(float4*)&As[r][q*4] = *(const float4*)(ab + (size_t)r*D_ + kc + q*4);
            int k = idx >> 4, f = idx & 15;
            *(float4*)&Bs[k][f*4] = *(const float4*)(Wo + (size_t)(kc+k)*D_ + nb*64 + f*4);
        }
        __syncthreads();
        #pragma unroll
        for (int k = 0; k < 32; k++) {
            float a0 = As[ty*4+0][k], a1 = As[ty*4+1][k];
            float a2 = As[ty*4+2][k], a3 = As[ty*4+3][k];
            float4 b4 = *(const float4*)&Bs[k][tx*4];
            acc[0][0] += a0*b4.x; acc[0][1] += a0*b4.y; acc[0][2] += a0*b4.z; acc[0][3] += a0*b4.w;
            acc[1][0] += a1*b4.x; acc[1][1] += a1*b4.y; acc[1][2] += a1*b4.z; acc[1][3] += a1*b4.w;
            acc[2][0] += a2*b4.x; acc[2][1] += a2*b4.y; acc[2][2] += a2*b4.z; acc[2][3] += a2*b4.w;
            acc[3][0] += a3*b4.x; acc[3][1] += a3*b4.y; acc[3][2] += a3*b4.z; acc[3][3] += a3*b4.w;
        }
    }

    float4 bo4 = *(const float4*)(bo + nb*64 + tx*4);
    #pragma unroll
    for (int i = 0; i < 4; i++) {
        size_t row = (size_t)mb*64 + ty*4 + i;
        *(float4*)&out[row*D_ + nb*64 + tx*4] =
            make_float4(acc[i][0]+bo4.x, acc[i][1]+bo4.y, acc[i][2]+bo4.z, acc[i][3]+bo4.w);
    }
}

// ---------------------------------------------------------------------------
extern "C" void kernel_launch(void* const* d_in, const int* in_sizes, int n_in,
                              void* d_out, int out_size)
{
    const float* x  = (const float*)d_in[0];
    const float* Wq = (const float*)d_in[1];
    const float* bq = (const float*)d_in[2];
    const float* Wk = (const float*)d_in[3];
    const float* bk = (const float*)d_in[4];
    const float* Wv = (const float*)d_in[5];
    const float* bv = (const float*)d_in[6];
    const float* Wo = (const float*)d_in[7];
    const float* bo = (const float*)d_in[8];
    float* out = (float*)d_out;

    (void)in_sizes; (void)n_in; (void)out_size;

    dim3 g1(S_/64, H_, B_);
    qkv_kernel<<<g1, 256>>>(x, Wq, bq, Wk, bk, Wv, bv);

    dim3 g2(S_/128, H_, B_);
    attn_kernel<<<g2, 256>>>();

    dim3 g3(D_/64, (B_*S_)/64);
    proj_kernel<<<g3, 256>>>(Wo, bo, out);
}

// round 3
// speedup vs baseline: 3.8929x; 1.9689x over previous
#include <cuda_runtime.h>
#include <math.h>
#include <stdint.h>

#define B_ 4
#define S_ 2048
#define D_ 512
#define H_ 8
#define E_ 64

// Scratch (static device memory — allocation-free per harness rules)
__device__ uint32_t g_qf[B_*H_*S_*E_];    // Q, A-frag order, scaled, tf32
__device__ uint32_t g_kf[B_*H_*S_*E_];    // K, B-frag order per 64-key tile
__device__ uint32_t g_vf[B_*H_*S_*E_];    // V, B-frag order per 64-key tile
__device__ uint32_t g_attf[B_*S_*D_];     // attention out, A-frag order, tf32
__device__ uint32_t g_wqf[H_*D_*E_];      // weights, B-frag order, tf32
__device__ uint32_t g_wkf[H_*D_*E_];
__device__ uint32_t g_wvf[H_*D_*E_];
__device__ uint32_t g_wof[D_*D_];

// ---------------------------------------------------------------------------
__device__ __forceinline__ uint32_t f2tf32(float f) {
    uint32_t u;
    asm("cvt.rna.tf32.f32 %0, %1;" : "=r"(u) : "f"(f));
    return u;
}

__device__ __forceinline__ void mma_tf32(float c[4],
                                         uint32_t a0, uint32_t a1,
                                         uint32_t a2, uint32_t a3,
                                         uint32_t b0, uint32_t b1) {
    asm volatile(
        "mma.sync.aligned.m16n8k8.row.col.f32.tf32.tf32.f32 "
        "{%0,%1,%2,%3}, {%4,%5,%6,%7}, {%8,%9}, {%0,%1,%2,%3};"
        : "+f"(c[0]), "+f"(c[1]), "+f"(c[2]), "+f"(c[3])
        : "r"(a0), "r"(a1), "r"(a2), "r"(a3), "r"(b0), "r"(b1));
}

__device__ __forceinline__ void cp16(uint32_t dst, const void* src) {
    asm volatile("cp.async.cg.shared.global [%0], [%1], 16;\n"
                 :: "r"(dst), "l"(src));
}

// ---------------------------------------------------------------------------
// Kernel 0: weight prep — tf32 + B-fragment order. 262144 threads, 1 elt each.
// ---------------------------------------------------------------------------
__global__ __launch_bounds__(256) void w_prep(
    const float* __restrict__ Wq, const float* __restrict__ Wk,
    const float* __restrict__ Wv, const float* __restrict__ Wo)
{
    int i = blockIdx.x*256 + threadIdx.x;   // 0..262143
    {   // Wq/Wk/Wv: [h][d][e] -> per-head, ks-major B-frag (k=d, n=e)
        int h = i >> 15, rem = i & 32767;
        int d = rem >> 6, e = rem & 63;
        int ks = d>>3, kl = d&7, tg = kl&3, r = kl>>2;
        int nt = e>>3, g = e&7;
        int idx = h*32768 + (ks*8+nt)*64 + (g*4+tg)*2 + r;
        g_wqf[idx] = f2tf32(Wq[i]);
        g_wkf[idx] = f2tf32(Wk[i]);
        g_wvf[idx] = f2tf32(Wv[i]);
    }
    {   // Wo: [d][n] -> nt-major B-frag (k=d, n)
        int d = i >> 9, n = i & 511;
        int ks = d>>3, kl = d&7, tg = kl&3, r = kl>>2;
        int nt = n>>3, g = n&7;
        g_wof[(nt*64+ks)*64 + (g*4+tg)*2 + r] = f2tf32(Wo[i]);
    }
}

// ---------------------------------------------------------------------------
// Kernel 1: QKV projection, tf32 MMA. CTA = 128 rows x 64 cols x {q,k,v} for
// one (b, h). Epilogue writes q in A-frag order (scaled), k/v in B-frag order.
// ---------------------------------------------------------------------------
__global__ __launch_bounds__(256, 2) void qkv_kernel(
    const float* __restrict__ x,
    const float* __restrict__ bq, const float* __restrict__ bk,
    const float* __restrict__ bv)
{
    __shared__ uint32_t XA[4096];            // X chunk 128x32, A-frag order
    __shared__ uint32_t WQs[2048], WKs[2048], WVs[2048];

    const int qb2 = blockIdx.x, h = blockIdx.y, b = blockIdx.z;
    const int tid = threadIdx.x;
    const int wp = tid >> 5, lane = tid & 31;
    const int g = lane >> 2, tg = lane & 3;

    float accq[8][4] = {}, acck[8][4] = {}, accv[8][4] = {};

    const float* xb = x + ((size_t)b*S_ + (size_t)qb2*128) * D_;
    const size_t wbase = (size_t)h * 32768;

    for (int kc = 0; kc < 16; kc++) {
        __syncthreads();
        // X tile -> A-frag smem (with tf32 cvt)
        #pragma unroll
        for (int j = 0; j < 4; j++) {
            int i4 = tid + j*256;
            int tt = i4 >> 3, q4 = i4 & 7;
            float4 xv = *(const float4*)(xb + (size_t)tt*D_ + kc*32 + q4*4);
            const float* xp = (const float*)&xv;
            int rb = tt >> 4, rr = tt & 15, hh = rr >> 3, gg = rr & 7;
            #pragma unroll
            for (int m = 0; m < 4; m++) {
                int kk = q4*4 + m;
                int ks = kk >> 3, kl = kk & 7, tgx = kl & 3, h2 = kl >> 2;
                XA[(rb*4+ks)*128 + (gg*4+tgx)*4 + (hh + 2*h2)] = f2tf32(xp[m]);
            }
        }
        // W tiles: pure uint4 copies (already frag-ordered tf32)
        #pragma unroll
        for (int j = 0; j < 2; j++) {
            int i4 = tid + j*256;
            ((uint4*)WQs)[i4] = *(const uint4*)(g_wqf + wbase + kc*2048 + i4*4);
            ((uint4*)WKs)[i4] = *(const uint4*)(g_wkf + wbase + kc*2048 + i4*4);
            ((uint4*)WVs)[i4] = *(const uint4*)(g_wvf + wbase + kc*2048 + i4*4);
        }
        __syncthreads();
        #pragma unroll
        for (int ksl = 0; ksl < 4; ksl++) {
            uint4 a = *(const uint4*)&XA[(wp*4+ksl)*128 + lane*4];
            #pragma unroll
            for (int nt = 0; nt < 8; nt++) {
                uint2 bb = *(const uint2*)&WQs[(ksl*8+nt)*64 + lane*2];
                mma_tf32(accq[nt], a.x, a.y, a.z, a.w, bb.x, bb.y);
            }
            #pragma unroll
            for (int nt = 0; nt < 8; nt++) {
                uint2 bb = *(const uint2*)&WKs[(ksl*8+nt)*64 + lane*2];
                mma_tf32(acck[nt], a.x, a.y, a.z, a.w, bb.x, bb.y);
            }
            #pragma unroll
            for (int nt = 0; nt < 8; nt++) {
                uint2 bb = *(const uint2*)&WVs[(ksl*8+nt)*64 + lane*2];
                mma_tf32(accv[nt], a.x, a.y, a.z, a.w, bb.x, bb.y);
            }
        }
    }

    // ---- epilogue: bias (+ scale for q) ----
    const float scale = rsqrtf((float)D_);
    #pragma unroll
    for (int nt = 0; nt < 8; nt++) {
        float2 b2q = *(const float2*)(bq + h*E_ + nt*8 + 2*tg);
        float2 b2k = *(const float2*)(bk + h*E_ + nt*8 + 2*tg);
        float2 b2v = *(const float2*)(bv + h*E_ + nt*8 + 2*tg);
        accq[nt][0] = (accq[nt][0]+b2q.x)*scale;
        accq[nt][1] = (accq[nt][1]+b2q.y)*scale;
        accq[nt][2] = (accq[nt][2]+b2q.x)*scale;
        accq[nt][3] = (accq[nt][3]+b2q.y)*scale;
        acck[nt][0] += b2k.x; acck[nt][1] += b2k.y;
        acck[nt][2] += b2k.x; acck[nt][3] += b2k.y;
        accv[nt][0] += b2v.x; accv[nt][1] += b2v.y;
        accv[nt][2] += b2v.x; accv[nt][3] += b2v.y;
    }

    // q: permute C->A layout via shuffles, store uint4 (coalesced)
    const size_t rbq = (size_t)(b*H_ + h)*(S_/16) + qb2*8 + wp;
    const int srcA = (lane & ~3) | (tg >> 1);
    const int srcB = srcA + 2;
    const bool hi = (tg & 1);
    #pragma unroll
    for (int ks = 0; ks < 8; ks++) {
        float x0 = __shfl_sync(0xffffffffu, accq[ks][0], srcA);
        float x1 = __shfl_sync(0xffffffffu, accq[ks][1], srcA);
        float z0 = __shfl_sync(0xffffffffu, accq[ks][2], srcA);
        float z1 = __shfl_sync(0xffffffffu, accq[ks][3], srcA);
        float y0 = __shfl_sync(0xffffffffu, accq[ks][0], srcB);
        float y1 = __shfl_sync(0xffffffffu, accq[ks][1], srcB);
        float u0 = __shfl_sync(0xffffffffu, accq[ks][2], srcB);
        float u1 = __shfl_sync(0xffffffffu, accq[ks][3], srcB);
        uint4 o4;
        o4.x = f2tf32(hi ? x1 : x0);
        o4.y = f2tf32(hi ? z1 : z0);
        o4.z = f2tf32(hi ? y1 : y0);
        o4.w = f2tf32(hi ? u1 : u0);
        *(uint4*)&g_qf[(rbq*8 + ks)*128 + lane*4] = o4;
    }

    // k, v: scatter into per-tile B-frag global layout
    const size_t tb0 = ((size_t)(b*H_ + h)*(S_/64) + qb2*2) * 4096;
    #pragma unroll
    for (int hh = 0; hh < 2; hh++) {
        int tt = wp*16 + hh*8 + g;                 // row within 128-row CTA
        size_t tbase = tb0 + (size_t)(tt >> 6) * 4096;
        int ntt = (tt & 63) >> 3;                  // key n-tile within 64-tile
        #pragma unroll
        for (int nt = 0; nt < 8; nt++) {
            #pragma unroll
            for (int c = 0; c < 2; c++) {
                // K as B of QK^T: k=e, n=tt
                int kl = 2*tg + c, tgk = kl & 3, r = kl >> 2;
                g_kf[tbase + (size_t)(ntt*8 + nt)*64 + (g*4 + tgk)*2 + r] =
                    f2tf32(acck[nt][hh*2 + c]);
                // V as B of PV: k=tt, n=e
                int g2 = 2*tg + c, tg2 = g & 3, r2 = g >> 2;
                g_vf[tbase + (size_t)(nt*8 + ntt)*64 + (g2*4 + tg2)*2 + r2] =
                    f2tf32(accv[nt][hh*2 + c]);
            }
        }
    }
}

// ---------------------------------------------------------------------------
// Kernel 2: causal flash attention, tf32 MMA, cp.async double-buffered tile
// copies (K/V already frag-ordered tf32 in global). Epilogue writes A-frag
// tf32 output for the projection GEMM.
// ---------------------------------------------------------------------------
__global__ __launch_bounds__(256, 2) void attn_kernel()
{
    extern __shared__ uint32_t smu[];   // 2 stages x (4096 K + 4096 V) words

    const int qb = (S_/128 - 1) - blockIdx.x;   // reversed for wave balance
    const int h = blockIdx.y, b = blockIdx.z;
    const int tid = threadIdx.x;
    const int wp = tid >> 5, lane = tid & 31;
    const int g = lane >> 2, tg = lane & 3;
    const size_t bhT = (size_t)(b*H_ + h) * (S_/64);
    const int qrow0 = qb*128 + wp*16 + g;

    uint32_t smem_base;
    asm("{ .reg .u64 t; cvta.to.shared.u64 t, %1; cvt.u32.u64 %0, t; }"
        : "=r"(smem_base) : "l"(smu));

    // Q fragments: direct uint4 loads (pre-scaled tf32 A-frag)
    uint4 aq[8];
    const size_t rbq = (size_t)(b*H_ + h)*(S_/16) + qb*8 + wp;
    #pragma unroll
    for (int ks = 0; ks < 8; ks++)
        aq[ks] = *(const uint4*)&g_qf[(rbq*8 + ks)*128 + lane*4];

    float o[8][4];
    #pragma unroll
    for (int nt = 0; nt < 8; nt++) { o[nt][0]=o[nt][1]=o[nt][2]=o[nt][3]=0.f; }
    float m0 = -1e30f, m1 = -1e30f, l0 = 0.f, l1 = 0.f;

    const int nk = 2*qb + 2;

    // prologue: stage 0 <- tile 0
    {
        const uint4* ksrc = (const uint4*)(g_kf + (bhT + 0)*4096);
        const uint4* vsrc = (const uint4*)(g_vf + (bhT + 0)*4096);
        #pragma unroll
        for (int j = 0; j < 4; j++) {
            int i4 = tid + j*256;
            cp16(smem_base + i4*16, ksrc + i4);
            cp16(smem_base + 16384 + i4*16, vsrc + i4);
        }
        asm volatile("cp.async.commit_group;");
    }

    for (int t = 0; t < nk; t++) {
        const int st = t & 1;
        if (t + 1 < nk) {
            uint32_t dst = smem_base + (st^1)*32768;
            const uint4* ksrc = (const uint4*)(g_kf + (bhT + t + 1)*4096);
            const uint4* vsrc = (const uint4*)(g_vf + (bhT + t + 1)*4096);
            #pragma unroll
            for (int j = 0; j < 4; j++) {
                int i4 = tid + j*256;
                cp16(dst + i4*16, ksrc + i4);
                cp16(dst + 16384 + i4*16, vsrc + i4);
            }
            asm volatile("cp.async.commit_group;");
            asm volatile("cp.async.wait_group 1;");
        } else {
            asm volatile("cp.async.wait_group 0;");
        }
        __syncthreads();

        const uint32_t* Kf = smu + st*8192;
        const uint32_t* Vf = Kf + 4096;

        // --- S = Q @ K^T ---
        float s[8][4];
        #pragma unroll
        for (int nt = 0; nt < 8; nt++) { s[nt][0]=s[nt][1]=s[nt][2]=s[nt][3]=0.f; }
        #pragma unroll
        for (int ks = 0; ks < 8; ks++) {
            #pragma unroll
            for (int nt = 0; nt < 8; nt++) {
                uint2 bb = *(const uint2*)&Kf[(nt*8 + ks)*64 + lane*2];
                mma_tf32(s[nt], aq[ks].x, aq[ks].y, aq[ks].z, aq[ks].w,
                         bb.x, bb.y);
            }
        }

        // --- causal mask on diagonal-crossing tiles ---
        if (t >= 2*qb) {
            #pragma unroll
            for (int nt = 0; nt < 8; nt++) {
                int c = t*64 + nt*8 + 2*tg;
                if (c     > qrow0)     s[nt][0] = -1e30f;
                if (c + 1 > qrow0)     s[nt][1] = -1e30f;
                if (c     > qrow0 + 8) s[nt][2] = -1e30f;
                if (c + 1 > qrow0 + 8) s[nt][3] = -1e30f;
            }
        }

        // --- online softmax (warp-local) ---
        float tm0 = -1e30f, tm1 = -1e30f;
        #pragma unroll
        for (int nt = 0; nt < 8; nt++) {
            tm0 = fmaxf(tm0, fmaxf(s[nt][0], s[nt][1]));
            tm1 = fmaxf(tm1, fmaxf(s[nt][2], s[nt][3]));
        }
        tm0 = fmaxf(tm0, __shfl_xor_sync(0xffffffffu, tm0, 1));
        tm0 = fmaxf(tm0, __shfl_xor_sync(0xffffffffu, tm0, 2));
        tm1 = fmaxf(tm1, __shfl_xor_sync(0xffffffffu, tm1, 1));
        tm1 = fmaxf(tm1, __shfl_xor_sync(0xffffffffu, tm1, 2));

        float mn0 = fmaxf(m0, tm0), mn1 = fmaxf(m1, tm1);
        float fc0 = __expf(m0 - mn0), fc1 = __expf(m1 - mn1);
        m0 = mn0; m1 = mn1;

        float rs0 = 0.f, rs1 = 0.f;
        #pragma unroll
        for (int nt = 0; nt < 8; nt++) {
            float p0 = __expf(s[nt][0] - mn0);
            float p1 = __expf(s[nt][1] - mn0);
            float p2 = __expf(s[nt][2] - mn1);
            float p3 = __expf(s[nt][3] - mn1);
            s[nt][0] = p0; s[nt][1] = p1; s[nt][2] = p2; s[nt][3] = p3;
            rs0 += p0 + p1; rs1 += p2 + p3;
        }
        rs0 += __shfl_xor_sync(0xffffffffu, rs0, 1);
        rs0 += __shfl_xor_sync(0xffffffffu, rs0, 2);
        rs1 += __shfl_xor_sync(0xffffffffu, rs1, 1);
        rs1 += __shfl_xor_sync(0xffffffffu, rs1, 2);
        l0 = l0*fc0 + rs0;
        l1 = l1*fc1 + rs1;
        #pragma unroll
        for (int nt = 0; nt < 8; nt++) {
            o[nt][0] *= fc0; o[nt][1] *= fc0;
            o[nt][2] *= fc1; o[nt][3] *= fc1;
        }

        // --- O += P @ V (permute P C->A via shuffles) ---
        const int srcA = (lane & ~3) | (tg >> 1);
        const int srcB = srcA + 2;
        const bool hi = (tg & 1);
        #pragma unroll
        for (int ks = 0; ks < 8; ks++) {
            float x0 = __shfl_sync(0xffffffffu, s[ks][0], srcA);
            float x1 = __shfl_sync(0xffffffffu, s[ks][1], srcA);
            float z0 = __shfl_sync(0xffffffffu, s[ks][2], srcA);
            float z1 = __shfl_sync(0xffffffffu, s[ks][3], srcA);
            float y0 = __shfl_sync(0xffffffffu, s[ks][0], srcB);
            float y1 = __shfl_sync(0xffffffffu, s[ks][1], srcB);
            float u0 = __shfl_sync(0xffffffffu, s[ks][2], srcB);
            float u1 = __shfl_sync(0xffffffffu, s[ks][3], srcB);
            uint32_t pa0 = f2tf32(hi ? x1 : x0);
            uint32_t pa1 = f2tf32(hi ? z1 : z0);
            uint32_t pa2 = f2tf32(hi ? y1 : y0);
            uint32_t pa3 = f2tf32(hi ? u1 : u0);
            #pragma unroll
            for (int nt = 0; nt < 8; nt++) {
                uint2 bb = *(const uint2*)&Vf[(nt*8 + ks)*64 + lane*2];
                mma_tf32(o[nt], pa0, pa1, pa2, pa3, bb.x, bb.y);
            }
        }
        __syncthreads();
    }

    // --- epilogue: normalize, permute C->A, store tf32 A-frag for proj ---
    const float inv0 = 1.f / l0, inv1 = 1.f / l1;
    #pragma unroll
    for (int nt = 0; nt < 8; nt++) {
        o[nt][0] *= inv0; o[nt][1] *= inv0;
        o[nt][2] *= inv1; o[nt][3] *= inv1;
    }
    const size_t rb = (size_t)b*(S_/16) + qb*8 + wp;
    const int srcA = (lane & ~3) | (tg >> 1);
    const int srcB = srcA + 2;
    const bool hi = (tg & 1);
    #pragma unroll
    for (int ks = 0; ks < 8; ks++) {
        float x0 = __shfl_sync(0xffffffffu, o[ks][0], srcA);
        float x1 = __shfl_sync(0xffffffffu, o[ks][1], srcA);
        float z0 = __shfl_sync(0xffffffffu, o[ks][2], srcA);
        float z1 = __shfl_sync(0xffffffffu, o[ks][3], srcA);
        float y0 = __shfl_sync(0xffffffffu, o[ks][0], srcB);
        float y1 = __shfl_sync(0xffffffffu, o[ks][1], srcB);
        float u0 = __shfl_sync(0xffffffffu, o[ks][2], srcB);
        float u1 = __shfl_sync(0xffffffffu, o[ks][3], srcB);
        uint4 o4;
        o4.x = f2tf32(hi ? x1 : x0);
        o4.y = f2tf32(hi ? z1 : z0);
        o4.z = f2tf32(hi ? y1 : y0);
        o4.w = f2tf32(hi ? u1 : u0);
        *(uint4*)&g_attf[(rb*64 + h*8 + ks)*128 + lane*4] = o4;
    }
}

// ---------------------------------------------------------------------------
// Kernel 3: output projection, tf32 MMA. CTA = 128 rows x 128 cols.
// ---------------------------------------------------------------------------
__global__ __launch_bounds__(256, 2) void proj_kernel(
    const float* __restrict__ bo, float* __restrict__ out)
{
    __shared__ uint32_t As[4096];   // 128 rows x 32 k, A-frag
    __shared__ uint32_t Bs[4096];   // 32 k x 128 n, B-frag

    const int cb = blockIdx.x, mb = blockIdx.y;
    const int tid = threadIdx.x;
    const int wp = tid >> 5, lane = tid & 31;
    const int g = lane >> 2, tg = lane & 3;

    float acc[16][4] = {};

    for (int kc = 0; kc < 16; kc++) {
        __syncthreads();
        #pragma unroll
        for (int j = 0; j < 4; j++) {
            int i = tid + j*256;      // 0..1023 uint4 each
            int rb_l = i >> 7, ksl = (i >> 5) & 3, off = i & 31;
            ((uint4*)As)[(rb_l*4 + ksl)*32 + off] =
                *(const uint4*)&g_attf[((size_t)(mb*8 + rb_l)*64 + kc*4 + ksl)*128 + off*4];
            int nt_l = i >> 6, ksl2 = (i >> 4) & 3, off2 = i & 15;
            ((uint4*)Bs)[(nt_l*4 + ksl2)*16 + off2] =
                *(const uint4*)&g_wof[((size_t)(cb*16 + nt_l)*64 + kc*4 + ksl2)*64 + off2*4];
        }
        __syncthreads();
        #pragma unroll
        for (int ksl = 0; ksl < 4; ksl++) {
            uint4 a = *(const uint4*)&As[(wp*4 + ksl)*128 + lane*4];
            #pragma unroll
            for (int nt = 0; nt < 16; nt++) {
                uint2 bb = *(const uint2*)&Bs[(nt*4 + ksl)*64 + lane*2];
                mma_tf32(acc[nt], a.x, a.y, a.z, a.w, bb.x, bb.y);
            }
        }
    }

    const int row0 = mb*128 + wp*16 + g;
    #pragma unroll
    for (int nt = 0; nt < 16; nt++) {
        int col = cb*128 + nt*8 + 2*tg;
        float2 b2 = *(const float2*)(bo + col);
        *(float2*)&out[(size_t)row0*D_ + col] =
            make_float2(acc[nt][0] + b2.x, acc[nt][1] + b2.y);
        *(float2*)&out[(size_t)(row0+8)*D_ + col] =
            make_float2(acc[nt][2] + b2.x, acc[nt][3] + b2.y);
    }
}

// ---------------------------------------------------------------------------
extern "C" void kernel_launch(void* const* d_in, const int* in_sizes, int n_in,
                              void* d_out, int out_size)
{
    const float* x  = (const float*)d_in[0];
    const float* Wq = (const float*)d_in[1];
    const float* bq = (const float*)d_in[2];
    const float* Wk = (const float*)d_in[3];
    const float* bk = (const float*)d_in[4];
    const float* Wv = (const float*)d_in[5];
    const float* bv = (const float*)d_in[6];
    const float* Wo = (const float*)d_in[7];
    const float* bo = (const float*)d_in[8];
    float* out = (float*)d_out;

    (void)in_sizes; (void)n_in; (void)out_size;

    cudaFuncSetAttribute(attn_kernel,
                         cudaFuncAttributeMaxDynamicSharedMemorySize, 65536);

    w_prep<<<1024, 256>>>(Wq, Wk, Wv, Wo);

    dim3 g1(S_/128, H_, B_);
    qkv_kernel<<<g1, 256>>>(x, bq, bk, bv);

    dim3 g2(S_/128, H_, B_);
    attn_kernel<<<g2, 256, 65536>>>();

    dim3 g3(D_/128, (B_*S_)/128);
    proj_kernel<<<g3, 256>>>(bo, out);
}

// round 4
// speedup vs baseline: 4.7754x; 1.2267x over previous
#include <cuda_runtime.h>
#include <math.h>
#include <stdint.h>

#define B_ 4
#define S_ 2048
#define D_ 512
#define H_ 8
#define E_ 64

// Scratch (static device memory — allocation-free per harness rules)
__device__ __align__(16) uint32_t g_xf[B_*S_*D_];     // X, A-frag order, tf32
__device__ __align__(16) uint32_t g_qf[B_*H_*S_*E_];  // Q, A-frag, scaled, tf32
__device__ __align__(16) uint32_t g_kf[B_*H_*S_*E_];  // K, B-frag per 64-key tile
__device__ __align__(16) uint32_t g_vf[B_*H_*S_*E_];  // V, B-frag per 64-key tile
__device__ __align__(16) uint32_t g_attf[B_*S_*D_];   // attn out, A-frag, tf32
__device__ __align__(16) uint32_t g_wqf[H_*D_*E_];    // weights, B-frag, tf32
__device__ __align__(16) uint32_t g_wkf[H_*D_*E_];
__device__ __align__(16) uint32_t g_wvf[H_*D_*E_];
__device__ __align__(16) uint32_t g_wof[D_*D_];

// ---------------------------------------------------------------------------
__device__ __forceinline__ uint32_t f2tf32(float f) {
    uint32_t u;
    asm("cvt.rna.tf32.f32 %0, %1;" : "=r"(u) : "f"(f));
    return u;
}

__device__ __forceinline__ void mma_tf32(float c[4],
                                         uint32_t a0, uint32_t a1,
                                         uint32_t a2, uint32_t a3,
                                         uint32_t b0, uint32_t b1) {
    asm volatile(
        "mma.sync.aligned.m16n8k8.row.col.f32.tf32.tf32.f32 "
        "{%0,%1,%2,%3}, {%4,%5,%6,%7}, {%8,%9}, {%0,%1,%2,%3};"
        : "+f"(c[0]), "+f"(c[1]), "+f"(c[2]), "+f"(c[3])
        : "r"(a0), "r"(a1), "r"(a2), "r"(a3), "r"(b0), "r"(b1));
}

__device__ __forceinline__ void cp16(uint32_t dst, const void* src) {
    asm volatile("cp.async.cg.shared.global [%0], [%1], 16;\n"
                 :: "r"(dst), "l"(src));
}

__device__ __forceinline__ uint32_t s2u(const void* p) {
    uint32_t a;
    asm("{ .reg .u64 t; cvta.to.shared.u64 t, %1; cvt.u32.u64 %0, t; }"
        : "=r"(a) : "l"(p));
    return a;
}

// ---------------------------------------------------------------------------
// Kernel 0a: weight prep — tf32 + B-fragment order.
// ---------------------------------------------------------------------------
__global__ __launch_bounds__(256) void w_prep(
    const float* __restrict__ Wq, const float* __restrict__ Wk,
    const float* __restrict__ Wv, const float* __restrict__ Wo)
{
    int i = blockIdx.x*256 + threadIdx.x;   // 0..262143
    {   // Wq/Wk/Wv: [h][d][e] -> per-head, ks-major B-frag (k=d, n=e)
        int h = i >> 15, rem = i & 32767;
        int d = rem >> 6, e = rem & 63;
        int ks = d>>3, kl = d&7, tg = kl&3, r = kl>>2;
        int nt = e>>3, g = e&7;
        int idx = h*32768 + (ks*8+nt)*64 + (g*4+tg)*2 + r;
        g_wqf[idx] = f2tf32(Wq[i]);
        g_wkf[idx] = f2tf32(Wk[i]);
        g_wvf[idx] = f2tf32(Wv[i]);
    }
    {   // Wo: [d][n] -> nt-major B-frag (k=d, n)
        int d = i >> 9, n = i & 511;
        int ks = d>>3, kl = d&7, tg = kl&3, r = kl>>2;
        int nt = n>>3, g = n&7;
        g_wof[(nt*64+ks)*64 + (g*4+tg)*2 + r] = f2tf32(Wo[i]);
    }
}

// ---------------------------------------------------------------------------
// Kernel 0b: X prep — tf32 + A-fragment order (done ONCE; previously the qkv
// kernel redid this per head = 8x). One uint4 (one A-frag slot) per thread.
// ---------------------------------------------------------------------------
__global__ __launch_bounds__(256) void x_prep(const float* __restrict__ x)
{
    int i = blockIdx.x*256 + threadIdx.x;      // uint4 index, 1M total
    int lane = i & 31;
    int ks = (i >> 5) & 63;                    // k-tile (D/8 = 64)
    int rbg = i >> 11;                         // global 16-row block, 0..511
    int g = lane >> 2, tg = lane & 3;
    const float* src = x + ((size_t)rbg*16 + g)*D_ + ks*8 + tg;
    uint4 o;
    o.x = f2tf32(src[0]);          // (row g,   k tg)
    o.y = f2tf32(src[8*D_]);       // (row g+8, k tg)
    o.z = f2tf32(src[4]);          // (row g,   k tg+4)
    o.w = f2tf32(src[8*D_ + 4]);   // (row g+8, k tg+4)
    *(uint4*)&g_xf[(size_t)i*4] = o;
}

// ---------------------------------------------------------------------------
// Kernel 1: QKV projection, tf32 MMA, 2-stage cp.async pipeline, pure-copy
// loads. CTA = 128 rows x 64 cols x {q,k,v} for one (b, h).
// Stage layout (words): XA[4096] WQ[2048] WK[2048] WV[2048] = 40KB/stage.
// ---------------------------------------------------------------------------
#define QKV_STAGE_W 10240
#define QKV_SMEM_B  (2*QKV_STAGE_W*4)

__global__ __launch_bounds__(256, 2) void qkv_kernel(
    const float* __restrict__ bq, const float* __restrict__ bk,
    const float* __restrict__ bv)
{
    extern __shared__ uint32_t smu[];

    const int qb2 = blockIdx.x, h = blockIdx.y, b = blockIdx.z;
    const int tid = threadIdx.x;
    const int wp = tid >> 5, lane = tid & 31;
    const int g = lane >> 2, tg = lane & 3;
    const uint32_t smem_base = s2u(smu);

    const size_t rbg0 = (size_t)b*(S_/16) + qb2*8;
    const size_t wbase = (size_t)h * 32768;

    float accq[8][4] = {}, acck[8][4] = {}, accv[8][4] = {};

    // ---- loader lambda-ish macro: stage st <- chunk kc ----
    #define QKV_LOAD(st, kc) do {                                             \
        uint32_t dst = smem_base + (st)*(QKV_STAGE_W*4);                      \
        _Pragma("unroll")                                                     \
        for (int j = 0; j < 4; j++) {                                         \
            int i = tid + j*256;                                              \
            int rb = i >> 7, ksl = (i >> 5) & 3, off = i & 31;                \
            cp16(dst + i*16,                                                  \
                 g_xf + ((rbg0 + rb)*64 + (kc)*4 + ksl)*128 + off*4);         \
        }                                                                     \
        _Pragma("unroll")                                                     \
        for (int j = 0; j < 2; j++) {                                         \
            int i = tid + j*256;                                              \
            cp16(dst + 16384 + i*16, g_wqf + wbase + (kc)*2048 + i*4);        \
            cp16(dst + 24576 + i*16, g_wkf + wbase + (kc)*2048 + i*4);        \
            cp16(dst + 32768 + i*16, g_wvf + wbase + (kc)*2048 + i*4);        \
        }                                                                     \
        asm volatile("cp.async.commit_group;");                               \
    } while (0)

    QKV_LOAD(0, 0);

    for (int kc = 0; kc < 16; kc++) {
        const int st = kc & 1;
        if (kc + 1 < 16) {
            QKV_LOAD(st^1, kc+1);
            asm volatile("cp.async.wait_group 1;");
        } else {
            asm volatile("cp.async.wait_group 0;");
        }
        __syncthreads();

        const uint32_t* XA  = smu + st*QKV_STAGE_W;
        const uint32_t* WQs = XA + 4096;
        const uint32_t* WKs = XA + 6144;
        const uint32_t* WVs = XA + 8192;

        #pragma unroll
        for (int ksl = 0; ksl < 4; ksl++) {
            uint4 a = *(const uint4*)&XA[(wp*4+ksl)*128 + lane*4];
            #pragma unroll
            for (int nt = 0; nt < 8; nt++) {
                uint2 bb = *(const uint2*)&WQs[(ksl*8+nt)*64 + lane*2];
                mma_tf32(accq[nt], a.x, a.y, a.z, a.w, bb.x, bb.y);
            }
            #pragma unroll
            for (int nt = 0; nt < 8; nt++) {
                uint2 bb = *(const uint2*)&WKs[(ksl*8+nt)*64 + lane*2];
                mma_tf32(acck[nt], a.x, a.y, a.z, a.w, bb.x, bb.y);
            }
            #pragma unroll
            for (int nt = 0; nt < 8; nt++) {
                uint2 bb = *(const uint2*)&WVs[(ksl*8+nt)*64 + lane*2];
                mma_tf32(accv[nt], a.x, a.y, a.z, a.w, bb.x, bb.y);
            }
        }
        __syncthreads();
    }
    #undef QKV_LOAD

    // ---- epilogue: bias (+ scale for q) ----
    const float scale = rsqrtf((float)D_);
    #pragma unroll
    for (int nt = 0; nt < 8; nt++) {
        float2 b2q = *(const float2*)(bq + h*E_ + nt*8 + 2*tg);
        float2 b2k = *(const float2*)(bk + h*E_ + nt*8 + 2*tg);
        float2 b2v = *(const float2*)(bv + h*E_ + nt*8 + 2*tg);
        accq[nt][0] = (accq[nt][0]+b2q.x)*scale;
        accq[nt][1] = (accq[nt][1]+b2q.y)*scale;
        accq[nt][2] = (accq[nt][2]+b2q.x)*scale;
        accq[nt][3] = (accq[nt][3]+b2q.y)*scale;
        acck[nt][0] += b2k.x; acck[nt][1] += b2k.y;
        acck[nt][2] += b2k.x; acck[nt][3] += b2k.y;
        accv[nt][0] += b2v.x; accv[nt][1] += b2v.y;
        accv[nt][2] += b2v.x; accv[nt][3] += b2v.y;
    }

    // q: permute C->A layout via shuffles, store uint4 (coalesced)
    const size_t rbq = (size_t)(b*H_ + h)*(S_/16) + qb2*8 + wp;
    const int srcA = (lane & ~3) | (tg >> 1);
    const int srcB = srcA + 2;
    const bool hi = (tg & 1);
    #pragma unroll
    for (int ks = 0; ks < 8; ks++) {
        float x0 = __shfl_sync(0xffffffffu, accq[ks][0], srcA);
        float x1 = __shfl_sync(0xffffffffu, accq[ks][1], srcA);
        float z0 = __shfl_sync(0xffffffffu, accq[ks][2], srcA);
        float z1 = __shfl_sync(0xffffffffu, accq[ks][3], srcA);
        float y0 = __shfl_sync(0xffffffffu, accq[ks][0], srcB);
        float y1 = __shfl_sync(0xffffffffu, accq[ks][1], srcB);
        float u0 = __shfl_sync(0xffffffffu, accq[ks][2], srcB);
        float u1 = __shfl_sync(0xffffffffu, accq[ks][3], srcB);
        uint4 o4;
        o4.x = f2tf32(hi ? x1 : x0);
        o4.y = f2tf32(hi ? z1 : z0);
        o4.z = f2tf32(hi ? y1 : y0);
        o4.w = f2tf32(hi ? u1 : u0);
        *(uint4*)&g_qf[(rbq*8 + ks)*128 + lane*4] = o4;
    }

    // k, v: scatter into per-tile B-frag global layout
    const size_t tb0 = ((size_t)(b*H_ + h)*(S_/64) + qb2*2) * 4096;
    #pragma unroll
    for (int hh = 0; hh < 2; hh++) {
        int tt = wp*16 + hh*8 + g;
        size_t tbase = tb0 + (size_t)(tt >> 6) * 4096;
        int ntt = (tt & 63) >> 3;
        #pragma unroll
        for (int nt = 0; nt < 8; nt++) {
            #pragma unroll
            for (int c = 0; c < 2; c++) {
                int kl = 2*tg + c, tgk = kl & 3, r = kl >> 2;
                g_kf[tbase + (size_t)(ntt*8 + nt)*64 + (g*4 + tgk)*2 + r] =
                    f2tf32(acck[nt][hh*2 + c]);
                int g2 = 2*tg + c, tg2 = g & 3, r2 = g >> 2;
                g_vf[tbase + (size_t)(nt*8 + ntt)*64 + (g2*4 + tg2)*2 + r2] =
                    f2tf32(accv[nt][hh*2 + c]);
            }
        }
    }
}

// ---------------------------------------------------------------------------
// Kernel 2: causal flash attention (unchanged from R3 — already cp.async 2x).
// ---------------------------------------------------------------------------
__global__ __launch_bounds__(256, 2) void attn_kernel()
{
    extern __shared__ uint32_t smu[];   // 2 stages x (4096 K + 4096 V) words

    const int qb = (S_/128 - 1) - blockIdx.x;
    const int h = blockIdx.y, b = blockIdx.z;
    const int tid = threadIdx.x;
    const int wp = tid >> 5, lane = tid & 31;
    const int g = lane >> 2, tg = lane & 3;
    const size_t bhT = (size_t)(b*H_ + h) * (S_/64);
    const int qrow0 = qb*128 + wp*16 + g;
    const uint32_t smem_base = s2u(smu);

    uint4 aq[8];
    const size_t rbq = (size_t)(b*H_ + h)*(S_/16) + qb*8 + wp;
    #pragma unroll
    for (int ks = 0; ks < 8; ks++)
        aq[ks] = *(const uint4*)&g_qf[(rbq*8 + ks)*128 + lane*4];

    float o[8][4];
    #pragma unroll
    for (int nt = 0; nt < 8; nt++) { o[nt][0]=o[nt][1]=o[nt][2]=o[nt][3]=0.f; }
    float m0 = -1e30f, m1 = -1e30f, l0 = 0.f, l1 = 0.f;

    const int nk = 2*qb + 2;

    {
        const uint4* ksrc = (const uint4*)(g_kf + (bhT + 0)*4096);
        const uint4* vsrc = (const uint4*)(g_vf + (bhT + 0)*4096);
        #pragma unroll
        for (int j = 0; j < 4; j++) {
            int i4 = tid + j*256;
            cp16(smem_base + i4*16, ksrc + i4);
            cp16(smem_base + 16384 + i4*16, vsrc + i4);
        }
        asm volatile("cp.async.commit_group;");
    }

    for (int t = 0; t < nk; t++) {
        const int st = t & 1;
        if (t + 1 < nk) {
            uint32_t dst = smem_base + (st^1)*32768;
            const uint4* ksrc = (const uint4*)(g_kf + (bhT + t + 1)*4096);
            const uint4* vsrc = (const uint4*)(g_vf + (bhT + t + 1)*4096);
            #pragma unroll
            for (int j = 0; j < 4; j++) {
                int i4 = tid + j*256;
                cp16(dst + i4*16, ksrc + i4);
                cp16(dst + 16384 + i4*16, vsrc + i4);
            }
            asm volatile("cp.async.commit_group;");
            asm volatile("cp.async.wait_group 1;");
        } else {
            asm volatile("cp.async.wait_group 0;");
        }
        __syncthreads();

        const uint32_t* Kf = smu + st*8192;
        const uint32_t* Vf = Kf + 4096;

        float s[8][4];
        #pragma unroll
        for (int nt = 0; nt < 8; nt++) { s[nt][0]=s[nt][1]=s[nt][2]=s[nt][3]=0.f; }
        #pragma unroll
        for (int ks = 0; ks < 8; ks++) {
            #pragma unroll
            for (int nt = 0; nt < 8; nt++) {
                uint2 bb = *(const uint2*)&Kf[(nt*8 + ks)*64 + lane*2];
                mma_tf32(s[nt], aq[ks].x, aq[ks].y, aq[ks].z, aq[ks].w,
                         bb.x, bb.y);
            }
        }

        if (t >= 2*qb) {
            #pragma unroll
            for (int nt = 0; nt < 8; nt++) {
                int c = t*64 + nt*8 + 2*tg;
                if (c     > qrow0)     s[nt][0] = -1e30f;
                if (c + 1 > qrow0)     s[nt][1] = -1e30f;
                if (c     > qrow0 + 8) s[nt][2] = -1e30f;
                if (c + 1 > qrow0 + 8) s[nt][3] = -1e30f;
            }
        }

        float tm0 = -1e30f, tm1 = -1e30f;
        #pragma unroll
        for (int nt = 0; nt < 8; nt++) {
            tm0 = fmaxf(tm0, fmaxf(s[nt][0], s[nt][1]));
            tm1 = fmaxf(tm1, fmaxf(s[nt][2], s[nt][3]));
        }
        tm0 = fmaxf(tm0, __shfl_xor_sync(0xffffffffu, tm0, 1));
        tm0 = fmaxf(tm0, __shfl_xor_sync(0xffffffffu, tm0, 2));
        tm1 = fmaxf(tm1, __shfl_xor_sync(0xffffffffu, tm1, 1));
        tm1 = fmaxf(tm1, __shfl_xor_sync(0xffffffffu, tm1, 2));

        float mn0 = fmaxf(m0, tm0), mn1 = fmaxf(m1, tm1);
        float fc0 = __expf(m0 - mn0), fc1 = __expf(m1 - mn1);
        m0 = mn0; m1 = mn1;

        float rs0 = 0.f, rs1 = 0.f;
        #pragma unroll
        for (int nt = 0; nt < 8; nt++) {
            float p0 = __expf(s[nt][0] - mn0);
            float p1 = __expf(s[nt][1] - mn0);
            float p2 = __expf(s[nt][2] - mn1);
            float p3 = __expf(s[nt][3] - mn1);
            s[nt][0] = p0; s[nt][1] = p1; s[nt][2] = p2; s[nt][3] = p3;
            rs0 += p0 + p1; rs1 += p2 + p3;
        }
        rs0 += __shfl_xor_sync(0xffffffffu, rs0, 1);
        rs0 += __shfl_xor_sync(0xffffffffu, rs0, 2);
        rs1 += __shfl_xor_sync(0xffffffffu, rs1, 1);
        rs1 += __shfl_xor_sync(0xffffffffu, rs1, 2);
        l0 = l0*fc0 + rs0;
        l1 = l1*fc1 + rs1;
        #pragma unroll
        for (int nt = 0; nt < 8; nt++) {
            o[nt][0] *= fc0; o[nt][1] *= fc0;
            o[nt][2] *= fc1; o[nt][3] *= fc1;
        }

        const int srcA = (lane & ~3) | (tg >> 1);
        const int srcB = srcA + 2;
        const bool hi = (tg & 1);
        #pragma unroll
        for (int ks = 0; ks < 8; ks++) {
            float x0 = __shfl_sync(0xffffffffu, s[ks][0], srcA);
            float x1 = __shfl_sync(0xffffffffu, s[ks][1], srcA);
            float z0 = __shfl_sync(0xffffffffu, s[ks][2], srcA);
            float z1 = __shfl_sync(0xffffffffu, s[ks][3], srcA);
            float y0 = __shfl_sync(0xffffffffu, s[ks][0], srcB);
            float y1 = __shfl_sync(0xffffffffu, s[ks][1], srcB);
            float u0 = __shfl_sync(0xffffffffu, s[ks][2], srcB);
            float u1 = __shfl_sync(0xffffffffu, s[ks][3], srcB);
            uint32_t pa0 = f2tf32(hi ? x1 : x0);
            uint32_t pa1 = f2tf32(hi ? z1 : z0);
            uint32_t pa2 = f2tf32(hi ? y1 : y0);
            uint32_t pa3 = f2tf32(hi ? u1 : u0);
            #pragma unroll
            for (int nt = 0; nt < 8; nt++) {
                uint2 bb = *(const uint2*)&Vf[(nt*8 + ks)*64 + lane*2];
                mma_tf32(o[nt], pa0, pa1, pa2, pa3, bb.x, bb.y);
            }
        }
        __syncthreads();
    }

    const float inv0 = 1.f / l0, inv1 = 1.f / l1;
    #pragma unroll
    for (int nt = 0; nt < 8; nt++) {
        o[nt][0] *= inv0; o[nt][1] *= inv0;
        o[nt][2] *= inv1; o[nt][3] *= inv1;
    }
    const size_t rb = (size_t)b*(S_/16) + qb*8 + wp;
    const int srcA = (lane & ~3) | (tg >> 1);
    const int srcB = srcA + 2;
    const bool hi = (tg & 1);
    #pragma unroll
    for (int ks = 0; ks < 8; ks++) {
        float x0 = __shfl_sync(0xffffffffu, o[ks][0], srcA);
        float x1 = __shfl_sync(0xffffffffu, o[ks][1], srcA);
        float z0 = __shfl_sync(0xffffffffu, o[ks][2], srcA);
        float z1 = __shfl_sync(0xffffffffu, o[ks][3], srcA);
        float y0 = __shfl_sync(0xffffffffu, o[ks][0], srcB);
        float y1 = __shfl_sync(0xffffffffu, o[ks][1], srcB);
        float u0 = __shfl_sync(0xffffffffu, o[ks][2], srcB);
        float u1 = __shfl_sync(0xffffffffu, o[ks][3], srcB);
        uint4 o4;
        o4.x = f2tf32(hi ? x1 : x0);
        o4.y = f2tf32(hi ? z1 : z0);
        o4.z = f2tf32(hi ? y1 : y0);
        o4.w = f2tf32(hi ? u1 : u0);
        *(uint4*)&g_attf[(rb*64 + h*8 + ks)*128 + lane*4] = o4;
    }
}

// ---------------------------------------------------------------------------
// Kernel 3: output projection, tf32 MMA, 2-stage cp.async pipeline.
// Stage layout (words): As[4096] Bs[4096] = 32KB/stage.
// ---------------------------------------------------------------------------
#define PROJ_STAGE_W 8192
#define PROJ_SMEM_B  (2*PROJ_STAGE_W*4)

__global__ __launch_bounds__(256, 2) void proj_kernel(
    const float* __restrict__ bo, float* __restrict__ out)
{
    extern __shared__ uint32_t smu[];

    const int cb = blockIdx.x, mb = blockIdx.y;
    const int tid = threadIdx.x;
    const int wp = tid >> 5, lane = tid & 31;
    const int g = lane >> 2, tg = lane & 3;
    const uint32_t smem_base = s2u(smu);

    float acc[16][4] = {};

    #define PROJ_LOAD(st, kc) do {                                            \
        uint32_t dst = smem_base + (st)*(PROJ_STAGE_W*4);                     \
        _Pragma("unroll")                                                     \
        for (int j = 0; j < 4; j++) {                                         \
            int i = tid + j*256;                                              \
            int rb_l = i >> 7, ksl = (i >> 5) & 3, off = i & 31;              \
            cp16(dst + i*16,                                                  \
                 g_attf + ((size_t)(mb*8 + rb_l)*64 + (kc)*4 + ksl)*128 + off*4); \
            int nt_l = i >> 6, ksl2 = (i >> 4) & 3, off2 = i & 15;            \
            cp16(dst + 16384 + i*16,                                          \
                 g_wof + ((size_t)(cb*16 + nt_l)*64 + (kc)*4 + ksl2)*64 + off2*4); \
        }                                                                     \
        asm volatile("cp.async.commit_group;");                               \
    } while (0)

    PROJ_LOAD(0, 0);

    for (int kc = 0; kc < 16; kc++) {
        const int st = kc & 1;
        if (kc + 1 < 16) {
            PROJ_LOAD(st^1, kc+1);
            asm volatile("cp.async.wait_group 1;");
        } else {
            asm volatile("cp.async.wait_group 0;");
        }
        __syncthreads();

        const uint32_t* As = smu + st*PROJ_STAGE_W;
        const uint32_t* Bs = As + 4096;

        #pragma unroll
        for (int ksl = 0; ksl < 4; ksl++) {
            uint4 a = *(const uint4*)&As[(wp*4 + ksl)*128 + lane*4];
            #pragma unroll
            for (int nt = 0; nt < 16; nt++) {
                uint2 bb = *(const uint2*)&Bs[(nt*4 + ksl)*64 + lane*2];
                mma_tf32(acc[nt], a.x, a.y, a.z, a.w, bb.x, bb.y);
            }
        }
        __syncthreads();
    }
    #undef PROJ_LOAD

    const int row0 = mb*128 + wp*16 + g;
    #pragma unroll
    for (int nt = 0; nt < 16; nt++) {
        int col = cb*128 + nt*8 + 2*tg;
        float2 b2 = *(const float2*)(bo + col);
        *(float2*)&out[(size_t)row0*D_ + col] =
            make_float2(acc[nt][0] + b2.x, acc[nt][1] + b2.y);
        *(float2*)&out[(size_t)(row0+8)*D_ + col] =
            make_float2(acc[nt][2] + b2.x, acc[nt][3] + b2.y);
    }
}

// ---------------------------------------------------------------------------
extern "C" void kernel_launch(void* const* d_in, const int* in_sizes, int n_in,
                              void* d_out, int out_size)
{
    const float* x  = (const float*)d_in[0];
    const float* Wq = (const float*)d_in[1];
    const float* bq = (const float*)d_in[2];
    const float* Wk = (const float*)d_in[3];
    const float* bk = (const float*)d_in[4];
    const float* Wv = (const float*)d_in[5];
    const float* bv = (const float*)d_in[6];
    const float* Wo = (const float*)d_in[7];
    const float* bo = (const float*)d_in[8];
    float* out = (float*)d_out;

    (void)in_sizes; (void)n_in; (void)out_size;

    cudaFuncSetAttribute(qkv_kernel,
                         cudaFuncAttributeMaxDynamicSharedMemorySize, QKV_SMEM_B);
    cudaFuncSetAttribute(attn_kernel,
                         cudaFuncAttributeMaxDynamicSharedMemorySize, 65536);
    cudaFuncSetAttribute(proj_kernel,
                         cudaFuncAttributeMaxDynamicSharedMemorySize, PROJ_SMEM_B);

    w_prep<<<1024, 256>>>(Wq, Wk, Wv, Wo);
    x_prep<<<4096, 256>>>(x);

    dim3 g1(S_/128, H_, B_);
    qkv_kernel<<<g1, 256, QKV_SMEM_B>>>(bq, bk, bv);

    dim3 g2(S_/128, H_, B_);
    attn_kernel<<<g2, 256, 65536>>>();

    dim3 g3(D_/128, (B_*S_)/128);
    proj_kernel<<<g3, 256, PROJ_SMEM_B>>>(bo, out);
}